// round 16
// baseline (speedup 1.0000x reference)
#include <cuda_runtime.h>
#include <cuda_bf16.h>
#include <cstdint>

#define NUM_CLASSES 1000
#define CPAD        1024                   // padded class count
#define FEAT_DIM    256
#define N_ROWS      262144
#define ALPHA       0.5f
#define NB          256                    // A-phase blocks
#define NT          256                    // threads per index block
#define ROWS_PER_B  (N_ROWS / NB)          // 1024
#define BC          64                     // BC-phase blocks (all co-resident)
#define CHUNK       512                    // rows per gather block
#define NCHUNK      (N_ROWS / CHUNK)       // 512 gather blocks

// Scratch (device globals — no allocation allowed).
__device__ int g_parthist_t[CPAD * NB];    // [class][block] — transposed
__device__ int g_blockbase[NB * CPAD];     // [block][class]
__device__ int g_totals[CPAD];
__device__ int g_offsets[NUM_CLASSES];
__device__ int g_counts[NUM_CLASSES];
__device__ int g_rank[N_ROWS];
__device__ int g_rowidx[N_ROWS];
__device__ __align__(16) float g_sums[NUM_CLASSES * FEAT_DIM];
__device__ unsigned g_cnt1 = 0, g_gen1 = 0;

// Spin barrier among BC co-resident blocks (self-resetting, replay-safe).
__device__ __forceinline__ void spin_barrier(unsigned* cnt, unsigned* gen, unsigned nb) {
    __syncthreads();
    if (threadIdx.x == 0) {
        __threadfence();
        unsigned g = atomicAdd(gen, 0u);
        unsigned old = atomicAdd(cnt, 1u);
        if (old == nb - 1) {
            atomicExch(cnt, 0u);
            __threadfence();
            atomicAdd(gen, 1u);
        } else {
            while (atomicAdd(gen, 0u) == g) __nanosleep(64);
        }
        __threadfence();
    }
    __syncthreads();
}

#define F4ADD(a, b) { (a).x += (b).x; (a).y += (b).y; (a).z += (b).z; (a).w += (b).w; }

__device__ __forceinline__ void red_add_v4(float* addr, float4 v) {
    asm volatile("red.global.add.v4.f32 [%0], {%1, %2, %3, %4};"
                 :: "l"(addr), "f"(v.x), "f"(v.y), "f"(v.z), "f"(v.w)
                 : "memory");
}

// ---------------------------------------------------------------------------
// K_A: per-block smem histogram + within-(block,class) ranks -> g_rank.
// Writes partial histogram transposed [class][block]. Zeros g_sums.
// ---------------------------------------------------------------------------
__global__ void __launch_bounds__(NT)
idxA_kernel(const int* __restrict__ labels) {
    __shared__ int shA[CPAD];
    int tid = threadIdx.x;
    int myB = blockIdx.x;

    // Zero the RED accumulator (64000 float4 across 65536 threads).
    {
        int i = myB * NT + tid;
        if (i < NUM_CLASSES * FEAT_DIM / 4)
            reinterpret_cast<float4*>(g_sums)[i] = make_float4(0.f, 0.f, 0.f, 0.f);
    }

#pragma unroll
    for (int c = tid; c < CPAD; c += NT) shA[c] = 0;
    __syncthreads();

    int4 L = reinterpret_cast<const int4*>(labels)[myB * (ROWS_PER_B / 4) + tid];
    int4 R;
    R.x = atomicAdd(&shA[L.x], 1);
    R.y = atomicAdd(&shA[L.y], 1);
    R.z = atomicAdd(&shA[L.z], 1);
    R.w = atomicAdd(&shA[L.w], 1);
    reinterpret_cast<int4*>(g_rank)[myB * (ROWS_PER_B / 4) + tid] = R;
    __syncthreads();

#pragma unroll
    for (int c = tid; c < CPAD; c += NT)
        g_parthist_t[c * NB + myB] = shA[c];
}

// ---------------------------------------------------------------------------
// K_BC: fused cross-block scan + place, 64 blocks, one spin barrier.
// Phase B: block owns 16 classes; 16 threads/class, each covering 16 blocks
//          (4 int4 loads), width-16 shfl segmented scan -> blockbase, totals.
// Phase C: every block scans the 1024 totals locally, then places the rows
//          of 4 A-blocks (4096 rows). Block 0 publishes offsets/counts.
// ---------------------------------------------------------------------------
__global__ void __launch_bounds__(NT)
idxBC_kernel(const int* __restrict__ labels) {
    __shared__ int shA[CPAD];   // phase C: scatter bases for current A-block
    __shared__ int shS[NT];     // phase C: block scan
    int tid = threadIdx.x;
    int myB = blockIdx.x;

    // --- Phase B ---
    {
        int j = tid >> 4;              // class slot 0..15
        int t = tid & 15;              // thread within class group
        int c = myB * 16 + j;
        const int4* ph4 = reinterpret_cast<const int4*>(&g_parthist_t[c * NB + 16 * t]);
        int4 v0 = ph4[0], v1 = ph4[1], v2 = ph4[2], v3 = ph4[3];
        int s = v0.x + v0.y + v0.z + v0.w + v1.x + v1.y + v1.z + v1.w
              + v2.x + v2.y + v2.z + v2.w + v3.x + v3.y + v3.z + v3.w;

        // Inclusive scan across the 16-thread segment (width-16 shfl).
        int sub = tid & 15;
        int inc = s;
#pragma unroll
        for (int off = 1; off < 16; off <<= 1) {
            int u = __shfl_up_sync(0xFFFFFFFFu, inc, off, 16);
            if (sub >= off) inc += u;
        }
        int run = inc - s;             // exclusive prefix over blocks 16t..

        int vv[16] = {v0.x, v0.y, v0.z, v0.w, v1.x, v1.y, v1.z, v1.w,
                      v2.x, v2.y, v2.z, v2.w, v3.x, v3.y, v3.z, v3.w};
#pragma unroll
        for (int k = 0; k < 16; k++) {
            g_blockbase[(16 * t + k) * CPAD + c] = run;
            run += vv[k];
        }
        if (t == 15) g_totals[c] = run;   // class total
    }

    spin_barrier(&g_cnt1, &g_gen1, BC);

    // --- Phase C: local scan of class totals -> offsets ---
    int4 T = *reinterpret_cast<const int4*>(&g_totals[tid * 4]);
    int mysum = T.x + T.y + T.z + T.w;
    shS[tid] = mysum;
    __syncthreads();
#pragma unroll
    for (int off = 1; off < NT; off <<= 1) {
        int v = (tid >= off) ? shS[tid - off] : 0;
        __syncthreads();
        shS[tid] += v;
        __syncthreads();
    }
    int e0 = shS[tid] - mysum;
    int e1 = e0 + T.x, e2 = e1 + T.y, e3 = e2 + T.z;

    if (myB == 0) {                 // publish for chunksum/finalize
        int c4 = tid * 4;
        if (c4 + 0 < NUM_CLASSES) { g_offsets[c4 + 0] = e0; g_counts[c4 + 0] = T.x; }
        if (c4 + 1 < NUM_CLASSES) { g_offsets[c4 + 1] = e1; g_counts[c4 + 1] = T.y; }
        if (c4 + 2 < NUM_CLASSES) { g_offsets[c4 + 2] = e2; g_counts[c4 + 2] = T.z; }
        if (c4 + 3 < NUM_CLASSES) { g_offsets[c4 + 3] = e3; g_counts[c4 + 3] = T.w; }
    }

    // Place the rows of 4 A-blocks (a = myB*4 .. myB*4+3).
#pragma unroll 1
    for (int q = 0; q < 4; q++) {
        int a = myB * 4 + q;
        int4 B = *reinterpret_cast<const int4*>(&g_blockbase[a * CPAD + tid * 4]);
        shA[tid * 4 + 0] = e0 + B.x;
        shA[tid * 4 + 1] = e1 + B.y;
        shA[tid * 4 + 2] = e2 + B.z;
        shA[tid * 4 + 3] = e3 + B.w;
        __syncthreads();

        int4 L = reinterpret_cast<const int4*>(labels)[a * (ROWS_PER_B / 4) + tid];
        int4 R = reinterpret_cast<const int4*>(g_rank)[a * (ROWS_PER_B / 4) + tid];
        int rowbase = a * ROWS_PER_B + tid * 4;
        g_rowidx[shA[L.x] + R.x] = rowbase + 0;
        g_rowidx[shA[L.y] + R.y] = rowbase + 1;
        g_rowidx[shA[L.z] + R.z] = rowbase + 2;
        g_rowidx[shA[L.w] + R.w] = rowbase + 3;
        __syncthreads();
    }
}

// ---------------------------------------------------------------------------
// K2: perfectly balanced gather — each block owns CHUNK consecutive entries
// of the class-sorted rowidx. (Unchanged — measured 70.6% DRAM, at the
// random-gather page-efficiency ceiling.)
// ---------------------------------------------------------------------------
__global__ void __launch_bounds__(256, 4)
chunksum_kernel(const float* __restrict__ features) {
    __shared__ float4 sred[256];
    int tid = threadIdx.x;
    int r4 = tid >> 6;   // row slot 0..3
    int c4 = tid & 63;   // float4 column 0..63
    const float4* __restrict__ f4 = reinterpret_cast<const float4*>(features);

    int s = blockIdx.x * CHUNK;
    int e = s + CHUNK;

    // Largest cls with offsets[cls] <= s  (offsets[0] == 0).
    int lo = 0, hi = NUM_CLASSES - 1;
    while (lo < hi) {
        int mid = (lo + hi + 1) >> 1;
        if (g_offsets[mid] <= s) lo = mid; else hi = mid - 1;
    }
    int cls = lo;
    int pos = s;

    while (pos < e) {
        while (cls < NUM_CLASSES - 1 && g_offsets[cls + 1] <= pos) cls++;
        int cend = g_offsets[cls] + g_counts[cls];
        int segend = min(e, cend);

        float4 a0 = make_float4(0.f, 0.f, 0.f, 0.f);
        float4 a1 = a0, a2 = a0, a3 = a0;

        int i = pos + r4;
        for (; i + 12 < segend; i += 16) {
            int i0 = g_rowidx[i];
            int i1 = g_rowidx[i + 4];
            int i2 = g_rowidx[i + 8];
            int i3 = g_rowidx[i + 12];
            float4 v0 = __ldcs(&f4[(size_t)i0 * 64 + c4]);
            float4 v1 = __ldcs(&f4[(size_t)i1 * 64 + c4]);
            float4 v2 = __ldcs(&f4[(size_t)i2 * 64 + c4]);
            float4 v3 = __ldcs(&f4[(size_t)i3 * 64 + c4]);
            F4ADD(a0, v0); F4ADD(a1, v1); F4ADD(a2, v2); F4ADD(a3, v3);
        }
        for (; i < segend; i += 4) {
            float4 v = __ldcs(&f4[(size_t)g_rowidx[i] * 64 + c4]);
            F4ADD(a0, v);
        }
        F4ADD(a0, a1); F4ADD(a2, a3); F4ADD(a0, a2);

        sred[tid] = a0;
        __syncthreads();
        if (tid < 64) {
            float4 t0 = sred[tid];
            float4 t1 = sred[tid + 64];
            float4 t2 = sred[tid + 128];
            float4 t3 = sred[tid + 192];
            F4ADD(t0, t1); F4ADD(t2, t3); F4ADD(t0, t2);
            red_add_v4(&g_sums[(size_t)cls * FEAT_DIM + tid * 4], t0);
        }
        __syncthreads();
        pos = segend;
    }
}

// ---------------------------------------------------------------------------
// K3: finalize — mean + EMA + output (64000 float4s).
// ---------------------------------------------------------------------------
__global__ void __launch_bounds__(256)
finalize_kernel(const float* __restrict__ centers, float* __restrict__ out) {
    int i = blockIdx.x * blockDim.x + threadIdx.x;      // float4 index
    if (i >= NUM_CLASSES * FEAT_DIM / 4) return;
    int cls = i >> 6;
    int n = g_counts[cls];
    float4 c = reinterpret_cast<const float4*>(centers)[i];
    float4 o = c;
    if (n > 0) {
        float4 t = reinterpret_cast<const float4*>(g_sums)[i];
        float scale = ALPHA / (float)n;
        o.x = (1.0f - ALPHA) * c.x + scale * t.x;
        o.y = (1.0f - ALPHA) * c.y + scale * t.y;
        o.z = (1.0f - ALPHA) * c.z + scale * t.z;
        o.w = (1.0f - ALPHA) * c.w + scale * t.w;
    }
    reinterpret_cast<float4*>(out)[i] = o;
}

// ---------------------------------------------------------------------------
// Launch: features f32 [N,256], labels i32 [N], centers f32 [1000,256].
// ---------------------------------------------------------------------------
extern "C" void kernel_launch(void* const* d_in, const int* in_sizes, int n_in,
                              void* d_out, int out_size) {
    const float* features = (const float*)d_in[0];
    const int* labels     = (const int*)d_in[1];
    const float* centers  = (const float*)d_in[2];
    float* out            = (float*)d_out;

    idxA_kernel<<<NB, NT>>>(labels);
    idxBC_kernel<<<BC, NT>>>(labels);
    chunksum_kernel<<<NCHUNK, 256>>>(features);
    finalize_kernel<<<NUM_CLASSES * FEAT_DIM / 4 / 256, 256>>>(centers, out);
}